// round 8
// baseline (speedup 1.0000x reference)
#include <cuda_runtime.h>
#include <cuda_fp16.h>
#include <stdint.h>
#include <math.h>

#define DMODEL 1024
#define DFF    4096
#define SV     196
#define SVP    256
#define QROWS  (4 * 2048)   // 8192

// ---------------------------------------------------------------------------
// Scratch (device globals; allocations forbidden)
// ---------------------------------------------------------------------------
__device__ __half g_tex1h[QROWS * DMODEL];
__device__ __half g_tex2h[QROWS * DMODEL];
__device__ __half g_vis1h[SVP * DMODEL];
__device__ __half g_vis2h[SVP * DMODEL];
__device__ __half g_Wqh[DMODEL * DMODEL];
__device__ __half g_Wkh[DMODEL * DMODEL];
__device__ __half g_Wvh[DMODEL * DMODEL];
__device__ __half g_Woh[DMODEL * DMODEL];
__device__ __half g_W1h[DFF * DMODEL];
__device__ __half g_W2h[DMODEL * DFF];
__device__ __half g_K1h[SVP * DMODEL];
__device__ __half g_K2h[SVP * DMODEL];
__device__ __half g_V1T[DMODEL * SVP];
__device__ __half g_V2T[DMODEL * SVP];
__device__ __half g_Qh [QROWS * DMODEL];
__device__ float  g_S  [QROWS * SVP];
__device__ __half g_S16[QROWS * SVP];
__device__ __half g_Ah [QROWS * DMODEL];
__device__ float  g_O  [QROWS * DMODEL];
__device__ float  g_o1 [QROWS * DMODEL];
__device__ float  g_o2 [QROWS * DMODEL];
__device__ float  g_P  [QROWS * DMODEL];
__device__ __half g_Ph [QROWS * DMODEL];
__device__ __half g_Hh [QROWS * DFF];
__device__ float  g_F  [QROWS * DMODEL];

// ---------------------------------------------------------------------------
// Helpers
// ---------------------------------------------------------------------------
#define SMEM_SWIZZLE_128B(off) ((off) ^ (((off) >> 3) & 0x70))

__device__ __forceinline__ void ldsm4(uint32_t addr,
    uint32_t& r0, uint32_t& r1, uint32_t& r2, uint32_t& r3)
{
    asm volatile("ldmatrix.sync.aligned.m8n8.x4.shared.b16 {%0,%1,%2,%3},[%4];\n"
        : "=r"(r0), "=r"(r1), "=r"(r2), "=r"(r3) : "r"(addr));
}

__device__ __forceinline__ void mma16816(float* c,
    const uint32_t* a, uint32_t b0, uint32_t b1)
{
    asm volatile(
        "mma.sync.aligned.m16n8k16.row.col.f32.f16.f16.f32 "
        "{%0,%1,%2,%3},{%4,%5,%6,%7},{%8,%9},{%0,%1,%2,%3};\n"
        : "+f"(c[0]), "+f"(c[1]), "+f"(c[2]), "+f"(c[3])
        : "r"(a[0]), "r"(a[1]), "r"(a[2]), "r"(a[3]), "r"(b0), "r"(b1));
}

__device__ __forceinline__ void cp16(uint32_t saddr, const void* gaddr, int sz)
{
    asm volatile("cp.async.cg.shared.global [%0], [%1], 16, %2;\n"
        :: "r"(saddr), "l"(gaddr), "r"(sz));
}

// ---------------------------------------------------------------------------
// HMMA GEMM:  C[M,N] = A[M,K] (f16 row-major) * B[N,K]^T (f16 row-major)
// CTA 128x256, 512 threads (16 warps: 2 M x 8 N, warp tile 64x32),
// BK=64 (128B rows, SW128 XOR swizzle), 3-stage cp.async pipeline.
// A rows >= Mreal load as zero; output rows >= Mreal store 0.
// Epilogue: optional bias[N] (f32), resid[M,N] (f32), relu;
//           outputs: outF (f32), outH (f16), outHT (f16 transposed, ld=SVP).
// ---------------------------------------------------------------------------
#define BM 128
#define BN 256
#define BK 64
#define ATILE_B (BM * 128)          // 16384
#define BTILE_B (BN * 128)          // 32768
#define STAGE_B (ATILE_B + BTILE_B) // 49152
#define NSTAGE 3
#define SMEM_DYN (NSTAGE * STAGE_B)

__global__ __launch_bounds__(512, 1) void hgemm_nt(
    const __half* __restrict__ A, const __half* __restrict__ B,
    int M, int N, int K, int Mreal,
    const float* __restrict__ bias, const float* __restrict__ resid,
    float* __restrict__ outF, __half* __restrict__ outH,
    __half* __restrict__ outHT, int relu)
{
    extern __shared__ __align__(1024) char dsm[];

    const int tid  = threadIdx.x;
    const int lane = tid & 31;
    const int wid  = tid >> 5;
    const int wm   = wid >> 3;      // 0..1  (*64 in M)
    const int wn   = wid & 7;       // 0..7  (*32 in N)
    const int m0 = blockIdx.y * BM;
    const int n0 = blockIdx.x * BN;

    const uint32_t base = (uint32_t)__cvta_generic_to_shared(dsm);

    float acc[4][4][4];
#pragma unroll
    for (int i = 0; i < 4; i++)
#pragma unroll
        for (int j = 0; j < 4; j++)
#pragma unroll
            for (int r = 0; r < 4; r++) acc[i][j][r] = 0.f;

    // load mapping: 16B chunks, 8 per 128B row. A: 1024 chunks, B: 2048.
    auto issue = [&](int chunk, int stage) {
        const int k0 = chunk * BK;
        const uint32_t sA = base + stage * STAGE_B;
        const uint32_t sB = sA + ATILE_B;
#pragma unroll
        for (int j = 0; j < 2; j++) {           // A: 2 chunks/thread
            int c = tid + j * 512;
            int row = c >> 3, col = c & 7;
            cp16(sA + SMEM_SWIZZLE_128B((uint32_t)(row * 128 + col * 16)),
                 A + (size_t)(m0 + row) * K + k0 + col * 8,
                 (m0 + row) < Mreal ? 16 : 0);
        }
#pragma unroll
        for (int j = 0; j < 4; j++) {           // B: 4 chunks/thread
            int c = tid + j * 512;
            int row = c >> 3, col = c & 7;
            cp16(sB + SMEM_SWIZZLE_128B((uint32_t)(row * 128 + col * 16)),
                 B + (size_t)(n0 + row) * K + k0 + col * 8, 16);
        }
        asm volatile("cp.async.commit_group;\n" ::: "memory");
    };

    const int nk = K / BK;
    issue(0, 0);
    if (nk > 1) issue(1, 1);

    for (int i = 0; i < nk; i++) {
        if (i + 2 < nk) issue(i + 2, (i + 2) % NSTAGE);

        if (i + 2 < nk)
            asm volatile("cp.async.wait_group 2;\n" ::: "memory");
        else if (i + 1 < nk)
            asm volatile("cp.async.wait_group 1;\n" ::: "memory");
        else
            asm volatile("cp.async.wait_group 0;\n" ::: "memory");
        __syncthreads();

        const int st = i % NSTAGE;
        const uint32_t sA = base + st * STAGE_B;
        const uint32_t sB = sA + ATILE_B;

#pragma unroll
        for (int kk = 0; kk < 4; kk++) {        // 4 x k16 per BK=64
            const int kb = kk * 32;             // byte offset of k16 step
            uint32_t a[4][4];
#pragma unroll
            for (int mi = 0; mi < 4; mi++) {
                uint32_t off = (uint32_t)(
                    (wm * 64 + mi * 16 + (lane & 15)) * 128 +
                    kb + ((lane >> 4) << 4));
                ldsm4(sA + SMEM_SWIZZLE_128B(off),
                      a[mi][0], a[mi][1], a[mi][2], a[mi][3]);
            }
            uint32_t b[2][4];
#pragma unroll
            for (int nj = 0; nj < 2; nj++) {
                uint32_t off = (uint32_t)(
                    (wn * 32 + nj * 16 + (lane & 7) + ((lane >> 4) << 3)) * 128 +
                    kb + (((lane >> 3) & 1) << 4));
                ldsm4(sB + SMEM_SWIZZLE_128B(off),
                      b[nj][0], b[nj][1], b[nj][2], b[nj][3]);
            }
#pragma unroll
            for (int mi = 0; mi < 4; mi++)
#pragma unroll
                for (int nf = 0; nf < 4; nf++) {
                    const int nj = nf >> 1;
                    uint32_t b0 = (nf & 1) ? b[nj][2] : b[nj][0];
                    uint32_t b1 = (nf & 1) ? b[nj][3] : b[nj][1];
                    mma16816(acc[mi][nf], a[mi], b0, b1);
                }
        }
        __syncthreads();
    }

    // Epilogue
#pragma unroll
    for (int mi = 0; mi < 4; mi++)
#pragma unroll
        for (int nf = 0; nf < 4; nf++)
#pragma unroll
            for (int r = 0; r < 4; r++) {
                int m = m0 + wm * 64 + mi * 16 + (lane >> 2) + ((r >= 2) ? 8 : 0);
                int n = n0 + wn * 32 + nf * 8 + (lane & 3) * 2 + (r & 1);
                float v = acc[mi][nf][r];
                if (bias)  v += bias[n];
                if (resid) v += resid[(size_t)m * N + n];
                if (relu)  v = fmaxf(v, 0.f);
                if (m >= Mreal) v = 0.f;
                if (outF)  outF[(size_t)m * N + n] = v;
                if (outH)  outH[(size_t)m * N + n] = __float2half_rn(v);
                if (outHT) outHT[(size_t)n * SVP + m] = __float2half_rn(v);
            }
}

// ---------------------------------------------------------------------------
// f32 -> f16 conversion
// ---------------------------------------------------------------------------
__global__ __launch_bounds__(256) void cvt4(
    const float* __restrict__ s, __half* __restrict__ d, int n4)
{
    int i = blockIdx.x * 256 + threadIdx.x;
    if (i < n4) {
        float4 v = ((const float4*)s)[i];
        __half2* dp = (__half2*)d;
        dp[2 * i + 0] = __floats2half2_rn(v.x, v.y);
        dp[2 * i + 1] = __floats2half2_rn(v.z, v.w);
    }
}

// ---------------------------------------------------------------------------
// Softmax over Sv=196 (S stride SVP, score stride SV); f16 out, zero pad
// ---------------------------------------------------------------------------
__global__ __launch_bounds__(256) void softmax_kernel(
    const float* __restrict__ S, const float* __restrict__ score,
    __half* __restrict__ S16)
{
    const int r = blockIdx.x;
    const int t = threadIdx.x;
    __shared__ float red[256];

    float myval = 0.f, v = -1e30f;
    if (t < SV) {
        myval = (S[(size_t)r * SVP + t] + score[(size_t)r * SV + t]) * 0.125f;
        v = myval;
    }
    red[t] = v;
    __syncthreads();
    for (int s = 128; s > 0; s >>= 1) {
        if (t < s) red[t] = fmaxf(red[t], red[t + s]);
        __syncthreads();
    }
    const float mx = red[0];
    __syncthreads();
    float e = (t < SV) ? __expf(myval - mx) : 0.f;
    red[t] = e;
    __syncthreads();
    for (int s = 128; s > 0; s >>= 1) {
        if (t < s) red[t] += red[t + s];
        __syncthreads();
    }
    const float inv = 1.f / red[0];
    S16[(size_t)r * SVP + t] = __float2half_rn((t < SV) ? e * inv : 0.f);
}

// ---------------------------------------------------------------------------
// LayerNorm over D=1024
// ---------------------------------------------------------------------------
__global__ __launch_bounds__(256) void layernorm_kernel(
    const float* __restrict__ X, const float* __restrict__ g,
    const float* __restrict__ b, float* __restrict__ Y)
{
    const int r = blockIdx.x;
    const int t = threadIdx.x;
    const float* x = X + (size_t)r * DMODEL;

    float vals[4];
    float s = 0.f, ss = 0.f;
#pragma unroll
    for (int i = 0; i < 4; i++) {
        float v = x[t + i * 256];
        vals[i] = v;
        s += v;
        ss += v * v;
    }
    __shared__ float rs[256], rss[256];
    rs[t] = s; rss[t] = ss;
    __syncthreads();
    for (int k = 128; k > 0; k >>= 1) {
        if (t < k) { rs[t] += rs[t + k]; rss[t] += rss[t + k]; }
        __syncthreads();
    }
    const float mu = rs[0] * (1.f / DMODEL);
    const float var = rss[0] * (1.f / DMODEL) - mu * mu;
    const float inv = rsqrtf(var + 1e-6f);
#pragma unroll
    for (int i = 0; i < 4; i++) {
        int c = t + i * 256;
        Y[(size_t)r * DMODEL + c] = (vals[i] - mu) * inv * g[c] + b[c];
    }
}

// ---------------------------------------------------------------------------
// Concat + MaxPool1d(k=2,s=2) -> P (f32) and Ph (f16)
// ---------------------------------------------------------------------------
__global__ __launch_bounds__(256) void pool_kernel(
    const float* __restrict__ o1, const float* __restrict__ o2,
    float* __restrict__ P, __half* __restrict__ Ph)
{
    size_t idx = (size_t)blockIdx.x * 256 + threadIdx.x;
    int c = (int)(idx & (DMODEL - 1));
    size_t r = idx >> 10;
    const float* src = (c < 512) ? (o1 + r * DMODEL + 2 * c)
                                 : (o2 + r * DMODEL + 2 * c - DMODEL);
    float v = fmaxf(src[0], src[1]);
    P[idx] = v;
    Ph[idx] = __float2half_rn(v);
}

// ---------------------------------------------------------------------------
// Host orchestration
// ---------------------------------------------------------------------------
extern "C" void kernel_launch(void* const* d_in, const int* in_sizes, int n_in,
                              void* d_out, int out_size)
{
    const float* text1 = (const float*)d_in[0];
    const float* vis1  = (const float*)d_in[1];
    const float* sc1   = (const float*)d_in[2];
    const float* text2 = (const float*)d_in[3];
    const float* vis2  = (const float*)d_in[4];
    const float* sc2   = (const float*)d_in[5];
    const float* Wq = (const float*)d_in[6],  *bq = (const float*)d_in[7];
    const float* Wk = (const float*)d_in[8],  *bk = (const float*)d_in[9];
    const float* Wv = (const float*)d_in[10], *bv = (const float*)d_in[11];
    const float* Wo = (const float*)d_in[12], *bo = (const float*)d_in[13];
    const float* W1 = (const float*)d_in[14], *b1 = (const float*)d_in[15];
    const float* W2 = (const float*)d_in[16], *b2 = (const float*)d_in[17];
    const float* g1 = (const float*)d_in[18], *be1 = (const float*)d_in[19];
    const float* g2 = (const float*)d_in[20], *be2 = (const float*)d_in[21];
    float* out = (float*)d_out;

    __half *tex1h, *tex2h, *vis1h, *vis2h, *Wqh, *Wkh, *Wvh, *Woh, *W1h, *W2h;
    __half *K1h, *K2h, *V1T, *V2T, *Qh, *S16, *Ah, *Ph, *Hh;
    float *S, *O, *o1, *o2, *P, *F;
    cudaGetSymbolAddress((void**)&tex1h, g_tex1h);
    cudaGetSymbolAddress((void**)&tex2h, g_tex2h);
    cudaGetSymbolAddress((void**)&vis1h, g_vis1h);
    cudaGetSymbolAddress((void**)&vis2h, g_vis2h);
    cudaGetSymbolAddress((void**)&Wqh, g_Wqh);
    cudaGetSymbolAddress((void**)&Wkh, g_Wkh);
    cudaGetSymbolAddress((void**)&Wvh, g_Wvh);
    cudaGetSymbolAddress((void**)&Woh, g_Woh);
    cudaGetSymbolAddress((void**)&W1h, g_W1h);
    cudaGetSymbolAddress((void**)&W2h, g_W2h);
    cudaGetSymbolAddress((void**)&K1h, g_K1h);
    cudaGetSymbolAddress((void**)&K2h, g_K2h);
    cudaGetSymbolAddress((void**)&V1T, g_V1T);
    cudaGetSymbolAddress((void**)&V2T, g_V2T);
    cudaGetSymbolAddress((void**)&Qh,  g_Qh);
    cudaGetSymbolAddress((void**)&S,   g_S);
    cudaGetSymbolAddress((void**)&S16, g_S16);
    cudaGetSymbolAddress((void**)&Ah,  g_Ah);
    cudaGetSymbolAddress((void**)&O,   g_O);
    cudaGetSymbolAddress((void**)&o1,  g_o1);
    cudaGetSymbolAddress((void**)&o2,  g_o2);
    cudaGetSymbolAddress((void**)&P,   g_P);
    cudaGetSymbolAddress((void**)&Ph,  g_Ph);
    cudaGetSymbolAddress((void**)&Hh,  g_Hh);
    cudaGetSymbolAddress((void**)&F,   g_F);

    static bool attr_done = false;
    if (!attr_done) {
        cudaFuncSetAttribute(hgemm_nt,
            cudaFuncAttributeMaxDynamicSharedMemorySize, SMEM_DYN);
        attr_done = true;
    }

    const dim3 blk(256);
    const dim3 gblk(512);
    auto cvt = [&](const float* s, __half* d, int n) {
        int n4 = n / 4;
        cvt4<<<(n4 + 255) / 256, blk>>>(s, d, n4);
    };
    cvt(text1, tex1h, QROWS * DMODEL);
    cvt(text2, tex2h, QROWS * DMODEL);
    cvt(vis1,  vis1h, SV * DMODEL);
    cvt(vis2,  vis2h, SV * DMODEL);
    cvt(Wq, Wqh, DMODEL * DMODEL);
    cvt(Wk, Wkh, DMODEL * DMODEL);
    cvt(Wv, Wvh, DMODEL * DMODEL);
    cvt(Wo, Woh, DMODEL * DMODEL);
    cvt(W1, W1h, DFF * DMODEL);
    cvt(W2, W2h, DMODEL * DFF);

    const dim3 gKV(DMODEL / BN, SVP / BM);      // 4 x 2
    const dim3 gProj(DMODEL / BN, QROWS / BM);  // 4 x 64
    const dim3 gScore(SVP / BN, QROWS / BM);    // 1 x 64
    const dim3 gFfn1(DFF / BN, QROWS / BM);     // 16 x 64

    // ---- K/V projections (M padded to 256, real 196) ----
    hgemm_nt<<<gKV, gblk, SMEM_DYN>>>(vis1h, Wkh, SVP, DMODEL, DMODEL, SV, bk,
                                      nullptr, nullptr, K1h, nullptr, 0);
    hgemm_nt<<<gKV, gblk, SMEM_DYN>>>(vis1h, Wvh, SVP, DMODEL, DMODEL, SV, bv,
                                      nullptr, nullptr, nullptr, V1T, 0);
    hgemm_nt<<<gKV, gblk, SMEM_DYN>>>(vis2h, Wkh, SVP, DMODEL, DMODEL, SV, bk,
                                      nullptr, nullptr, K2h, nullptr, 0);
    hgemm_nt<<<gKV, gblk, SMEM_DYN>>>(vis2h, Wvh, SVP, DMODEL, DMODEL, SV, bv,
                                      nullptr, nullptr, nullptr, V2T, 0);

    // ---- Branch 1 ----
    hgemm_nt<<<gProj, gblk, SMEM_DYN>>>(tex1h, Wqh, QROWS, DMODEL, DMODEL, QROWS,
                                        bq, nullptr, nullptr, Qh, nullptr, 0);
    hgemm_nt<<<gScore, gblk, SMEM_DYN>>>(Qh, K1h, QROWS, SVP, DMODEL, QROWS,
                                         nullptr, nullptr, S, nullptr, nullptr, 0);
    softmax_kernel<<<QROWS, blk>>>(S, sc1, S16);
    hgemm_nt<<<gProj, gblk, SMEM_DYN>>>(S16, V1T, QROWS, DMODEL, SVP, QROWS,
                                        nullptr, nullptr, nullptr, Ah, nullptr, 0);
    hgemm_nt<<<gProj, gblk, SMEM_DYN>>>(Ah, Woh, QROWS, DMODEL, DMODEL, QROWS,
                                        bo, text1, O, nullptr, nullptr, 0);
    layernorm_kernel<<<QROWS, blk>>>(O, g1, be1, o1);

    // ---- Branch 2 ----
    hgemm_nt<<<gProj, gblk, SMEM_DYN>>>(tex2h, Wqh, QROWS, DMODEL, DMODEL, QROWS,
                                        bq, nullptr, nullptr, Qh, nullptr, 0);
    hgemm_nt<<<gScore, gblk, SMEM_DYN>>>(Qh, K2h, QROWS, SVP, DMODEL, QROWS,
                                         nullptr, nullptr, S, nullptr, nullptr, 0);
    softmax_kernel<<<QROWS, blk>>>(S, sc2, S16);
    hgemm_nt<<<gProj, gblk, SMEM_DYN>>>(S16, V2T, QROWS, DMODEL, SVP, QROWS,
                                        nullptr, nullptr, nullptr, Ah, nullptr, 0);
    hgemm_nt<<<gProj, gblk, SMEM_DYN>>>(Ah, Woh, QROWS, DMODEL, DMODEL, QROWS,
                                        bo, text2, O, nullptr, nullptr, 0);
    layernorm_kernel<<<QROWS, blk>>>(O, g1, be1, o2);

    // ---- Concat + MaxPool ----
    pool_kernel<<<(QROWS * DMODEL) / 256, blk>>>(o1, o2, P, Ph);

    // ---- FFN + residual + final LN ----
    hgemm_nt<<<gFfn1, gblk, SMEM_DYN>>>(Ph, W1h, QROWS, DFF, DMODEL, QROWS,
                                        b1, nullptr, nullptr, Hh, nullptr, 1);
    hgemm_nt<<<gProj, gblk, SMEM_DYN>>>(Hh, W2h, QROWS, DMODEL, DFF, QROWS,
                                        b2, P, F, nullptr, nullptr, 0);
    layernorm_kernel<<<QROWS, blk>>>(F, g2, be2, out);
}

// round 13
// speedup vs baseline: 1.7382x; 1.7382x over previous
#include <cuda_runtime.h>
#include <cuda_fp16.h>
#include <stdint.h>
#include <math.h>

#define DMODEL 1024
#define DFF    4096
#define SV     196
#define SVP    256
#define QROWS  (4 * 2048)   // 8192

// ---------------------------------------------------------------------------
// Scratch (device globals; allocations forbidden)
// ---------------------------------------------------------------------------
__device__ __half g_tex1h[QROWS * DMODEL];
__device__ __half g_tex2h[QROWS * DMODEL];
__device__ __half g_vis1h[SVP * DMODEL];
__device__ __half g_vis2h[SVP * DMODEL];
__device__ __half g_Wqh[DMODEL * DMODEL];
__device__ __half g_Wkh[DMODEL * DMODEL];
__device__ __half g_Wvh[DMODEL * DMODEL];
__device__ __half g_Woh[DMODEL * DMODEL];
__device__ __half g_W1h[DFF * DMODEL];
__device__ __half g_W2h[DMODEL * DFF];
__device__ __half g_K1h[SVP * DMODEL];
__device__ __half g_K2h[SVP * DMODEL];
__device__ __half g_V1T[DMODEL * SVP];
__device__ __half g_V2T[DMODEL * SVP];
__device__ __half g_Qh [QROWS * DMODEL];
__device__ float  g_S  [QROWS * SVP];
__device__ __half g_S16[QROWS * SVP];
__device__ __half g_Ah [QROWS * DMODEL];
__device__ float  g_O  [QROWS * DMODEL];
__device__ float  g_o1 [QROWS * DMODEL];
__device__ float  g_o2 [QROWS * DMODEL];
__device__ float  g_P  [QROWS * DMODEL];
__device__ __half g_Ph [QROWS * DMODEL];
__device__ __half g_Hh [QROWS * DFF];
__device__ float  g_F  [QROWS * DMODEL];

// ---------------------------------------------------------------------------
// Helpers
// ---------------------------------------------------------------------------
#define SMEM_SWIZZLE_128B(off) ((off) ^ (((off) >> 3) & 0x70))

__device__ __forceinline__ void ldsm4(uint32_t addr,
    uint32_t& r0, uint32_t& r1, uint32_t& r2, uint32_t& r3)
{
    asm volatile("ldmatrix.sync.aligned.m8n8.x4.shared.b16 {%0,%1,%2,%3},[%4];\n"
        : "=r"(r0), "=r"(r1), "=r"(r2), "=r"(r3) : "r"(addr));
}

__device__ __forceinline__ void mma16816(float* c,
    const uint32_t* a, uint32_t b0, uint32_t b1)
{
    asm volatile(
        "mma.sync.aligned.m16n8k16.row.col.f32.f16.f16.f32 "
        "{%0,%1,%2,%3},{%4,%5,%6,%7},{%8,%9},{%0,%1,%2,%3};\n"
        : "+f"(c[0]), "+f"(c[1]), "+f"(c[2]), "+f"(c[3])
        : "r"(a[0]), "r"(a[1]), "r"(a[2]), "r"(a[3]), "r"(b0), "r"(b1));
}

__device__ __forceinline__ void cp16(uint32_t saddr, const void* gaddr, int sz)
{
    asm volatile("cp.async.cg.shared.global [%0], [%1], 16, %2;\n"
        :: "r"(saddr), "l"(gaddr), "r"(sz));
}

// ---------------------------------------------------------------------------
// HMMA GEMM:  C[M,N] = A[M,K] (f16 row-major) * B[N,K]^T (f16 row-major)
// CTA 128x128, 256 threads (8 warps: 4 M x 2 N, warp tile 32x64),
// BK=64 (128B rows, SW128 XOR swizzle), 3-stage cp.async, 2 CTAs/SM.
// A rows >= Mreal load as zero; output rows >= Mreal store 0.
// Epilogue: optional bias[N] (f32), resid[M,N] (f32), relu;
//           outputs: outF (f32), outH (f16), outHT (f16 transposed, ld=SVP).
// ---------------------------------------------------------------------------
#define BM 128
#define BN 128
#define BK 64
#define ATILE_B (BM * 128)          // 16384
#define BTILE_B (BN * 128)          // 16384
#define STAGE_B (ATILE_B + BTILE_B) // 32768
#define NSTAGE 3
#define SMEM_DYN (NSTAGE * STAGE_B) // 98304

__global__ __launch_bounds__(256, 2) void hgemm_nt(
    const __half* __restrict__ A, const __half* __restrict__ B,
    int M, int N, int K, int Mreal,
    const float* __restrict__ bias, const float* __restrict__ resid,
    float* __restrict__ outF, __half* __restrict__ outH,
    __half* __restrict__ outHT, int relu)
{
    extern __shared__ __align__(1024) char dsm[];

    const int tid  = threadIdx.x;
    const int lane = tid & 31;
    const int wid  = tid >> 5;
    const int warp_m = wid & 3;     // *32 in M
    const int warp_n = wid >> 2;    // *64 in N
    const int m0 = blockIdx.y * BM;
    const int n0 = blockIdx.x * BN;

    const uint32_t base = (uint32_t)__cvta_generic_to_shared(dsm);

    float acc[2][8][4];
#pragma unroll
    for (int i = 0; i < 2; i++)
#pragma unroll
        for (int j = 0; j < 8; j++)
#pragma unroll
            for (int r = 0; r < 4; r++) acc[i][j][r] = 0.f;

    // load mapping: 16B chunks, 8 per 128B row; A/B each 1024 chunks.
    auto issue = [&](int chunk, int stage) {
        const int k0 = chunk * BK;
        const uint32_t sA = base + stage * STAGE_B;
        const uint32_t sB = sA + ATILE_B;
#pragma unroll
        for (int j = 0; j < 4; j++) {
            int c = tid + j * 256;
            int row = c >> 3, col = c & 7;
            cp16(sA + SMEM_SWIZZLE_128B((uint32_t)(row * 128 + col * 16)),
                 A + (size_t)(m0 + row) * K + k0 + col * 8,
                 (m0 + row) < Mreal ? 16 : 0);
        }
#pragma unroll
        for (int j = 0; j < 4; j++) {
            int c = tid + j * 256;
            int row = c >> 3, col = c & 7;
            cp16(sB + SMEM_SWIZZLE_128B((uint32_t)(row * 128 + col * 16)),
                 B + (size_t)(n0 + row) * K + k0 + col * 8, 16);
        }
        asm volatile("cp.async.commit_group;\n" ::: "memory");
    };

    const int nk = K / BK;
    issue(0, 0);
    if (nk > 1) issue(1, 1);

    for (int i = 0; i < nk; i++) {
        if (i + 2 < nk) issue(i + 2, (i + 2) % NSTAGE);

        if (i + 2 < nk)
            asm volatile("cp.async.wait_group 2;\n" ::: "memory");
        else if (i + 1 < nk)
            asm volatile("cp.async.wait_group 1;\n" ::: "memory");
        else
            asm volatile("cp.async.wait_group 0;\n" ::: "memory");
        __syncthreads();

        const int st = i % NSTAGE;
        const uint32_t sA = base + st * STAGE_B;
        const uint32_t sB = sA + ATILE_B;

#pragma unroll
        for (int kk = 0; kk < 4; kk++) {        // 4 x k16 per BK=64
            const int kb = kk * 32;             // byte offset of this k16
            uint32_t a[2][4];
#pragma unroll
            for (int mi = 0; mi < 2; mi++) {
                uint32_t off = (uint32_t)(
                    (warp_m * 32 + mi * 16 + (lane & 15)) * 128 +
                    kb + ((lane >> 4) << 4));
                ldsm4(sA + SMEM_SWIZZLE_128B(off),
                      a[mi][0], a[mi][1], a[mi][2], a[mi][3]);
            }
            uint32_t b[4][4];
#pragma unroll
            for (int nj = 0; nj < 4; nj++) {
                uint32_t off = (uint32_t)(
                    (warp_n * 64 + nj * 16 + (lane & 7) + ((lane >> 4) << 3)) * 128 +
                    kb + (((lane >> 3) & 1) << 4));
                ldsm4(sB + SMEM_SWIZZLE_128B(off),
                      b[nj][0], b[nj][1], b[nj][2], b[nj][3]);
            }
#pragma unroll
            for (int mi = 0; mi < 2; mi++)
#pragma unroll
                for (int nf = 0; nf < 8; nf++) {
                    const int nj = nf >> 1;
                    uint32_t b0 = (nf & 1) ? b[nj][2] : b[nj][0];
                    uint32_t b1 = (nf & 1) ? b[nj][3] : b[nj][1];
                    mma16816(acc[mi][nf], a[mi], b0, b1);
                }
        }
        __syncthreads();
    }

    // Epilogue
#pragma unroll
    for (int mi = 0; mi < 2; mi++)
#pragma unroll
        for (int nf = 0; nf < 8; nf++)
#pragma unroll
            for (int r = 0; r < 4; r++) {
                int m = m0 + warp_m * 32 + mi * 16 + (lane >> 2) + ((r >= 2) ? 8 : 0);
                int n = n0 + warp_n * 64 + nf * 8 + (lane & 3) * 2 + (r & 1);
                float v = acc[mi][nf][r];
                if (bias)  v += bias[n];
                if (resid) v += resid[(size_t)m * N + n];
                if (relu)  v = fmaxf(v, 0.f);
                if (m >= Mreal) v = 0.f;
                if (outF)  outF[(size_t)m * N + n] = v;
                if (outH)  outH[(size_t)m * N + n] = __float2half_rn(v);
                if (outHT) outHT[(size_t)n * SVP + m] = __float2half_rn(v);
            }
}

// ---------------------------------------------------------------------------
// f32 -> f16 conversion
// ---------------------------------------------------------------------------
__global__ __launch_bounds__(256) void cvt4(
    const float* __restrict__ s, __half* __restrict__ d, int n4)
{
    int i = blockIdx.x * 256 + threadIdx.x;
    if (i < n4) {
        float4 v = ((const float4*)s)[i];
        __half2* dp = (__half2*)d;
        dp[2 * i + 0] = __floats2half2_rn(v.x, v.y);
        dp[2 * i + 1] = __floats2half2_rn(v.z, v.w);
    }
}

// ---------------------------------------------------------------------------
// Softmax over Sv=196 (S stride SVP, score stride SV); f16 out, zero pad
// ---------------------------------------------------------------------------
__global__ __launch_bounds__(256) void softmax_kernel(
    const float* __restrict__ S, const float* __restrict__ score,
    __half* __restrict__ S16)
{
    const int r = blockIdx.x;
    const int t = threadIdx.x;
    __shared__ float red[256];

    float myval = 0.f, v = -1e30f;
    if (t < SV) {
        myval = (S[(size_t)r * SVP + t] + score[(size_t)r * SV + t]) * 0.125f;
        v = myval;
    }
    red[t] = v;
    __syncthreads();
    for (int s = 128; s > 0; s >>= 1) {
        if (t < s) red[t] = fmaxf(red[t], red[t + s]);
        __syncthreads();
    }
    const float mx = red[0];
    __syncthreads();
    float e = (t < SV) ? __expf(myval - mx) : 0.f;
    red[t] = e;
    __syncthreads();
    for (int s = 128; s > 0; s >>= 1) {
        if (t < s) red[t] += red[t + s];
        __syncthreads();
    }
    const float inv = 1.f / red[0];
    S16[(size_t)r * SVP + t] = __float2half_rn((t < SV) ? e * inv : 0.f);
}

// ---------------------------------------------------------------------------
// LayerNorm over D=1024
// ---------------------------------------------------------------------------
__global__ __launch_bounds__(256) void layernorm_kernel(
    const float* __restrict__ X, const float* __restrict__ g,
    const float* __restrict__ b, float* __restrict__ Y)
{
    const int r = blockIdx.x;
    const int t = threadIdx.x;
    const float* x = X + (size_t)r * DMODEL;

    float vals[4];
    float s = 0.f, ss = 0.f;
#pragma unroll
    for (int i = 0; i < 4; i++) {
        float v = x[t + i * 256];
        vals[i] = v;
        s += v;
        ss += v * v;
    }
    __shared__ float rs[256], rss[256];
    rs[t] = s; rss[t] = ss;
    __syncthreads();
    for (int k = 128; k > 0; k >>= 1) {
        if (t < k) { rs[t] += rs[t + k]; rss[t] += rss[t + k]; }
        __syncthreads();
    }
    const float mu = rs[0] * (1.f / DMODEL);
    const float var = rss[0] * (1.f / DMODEL) - mu * mu;
    const float inv = rsqrtf(var + 1e-6f);
#pragma unroll
    for (int i = 0; i < 4; i++) {
        int c = t + i * 256;
        Y[(size_t)r * DMODEL + c] = (vals[i] - mu) * inv * g[c] + b[c];
    }
}

// ---------------------------------------------------------------------------
// Concat + MaxPool1d(k=2,s=2) -> P (f32) and Ph (f16)
// ---------------------------------------------------------------------------
__global__ __launch_bounds__(256) void pool_kernel(
    const float* __restrict__ o1, const float* __restrict__ o2,
    float* __restrict__ P, __half* __restrict__ Ph)
{
    size_t idx = (size_t)blockIdx.x * 256 + threadIdx.x;
    int c = (int)(idx & (DMODEL - 1));
    size_t r = idx >> 10;
    const float* src = (c < 512) ? (o1 + r * DMODEL + 2 * c)
                                 : (o2 + r * DMODEL + 2 * c - DMODEL);
    float v = fmaxf(src[0], src[1]);
    P[idx] = v;
    Ph[idx] = __float2half_rn(v);
}

// ---------------------------------------------------------------------------
// Host orchestration
// ---------------------------------------------------------------------------
extern "C" void kernel_launch(void* const* d_in, const int* in_sizes, int n_in,
                              void* d_out, int out_size)
{
    const float* text1 = (const float*)d_in[0];
    const float* vis1  = (const float*)d_in[1];
    const float* sc1   = (const float*)d_in[2];
    const float* text2 = (const float*)d_in[3];
    const float* vis2  = (const float*)d_in[4];
    const float* sc2   = (const float*)d_in[5];
    const float* Wq = (const float*)d_in[6],  *bq = (const float*)d_in[7];
    const float* Wk = (const float*)d_in[8],  *bk = (const float*)d_in[9];
    const float* Wv = (const float*)d_in[10], *bv = (const float*)d_in[11];
    const float* Wo = (const float*)d_in[12], *bo = (const float*)d_in[13];
    const float* W1 = (const float*)d_in[14], *b1 = (const float*)d_in[15];
    const float* W2 = (const float*)d_in[16], *b2 = (const float*)d_in[17];
    const float* g1 = (const float*)d_in[18], *be1 = (const float*)d_in[19];
    const float* g2 = (const float*)d_in[20], *be2 = (const float*)d_in[21];
    float* out = (float*)d_out;

    __half *tex1h, *tex2h, *vis1h, *vis2h, *Wqh, *Wkh, *Wvh, *Woh, *W1h, *W2h;
    __half *K1h, *K2h, *V1T, *V2T, *Qh, *S16, *Ah, *Ph, *Hh;
    float *S, *O, *o1, *o2, *P, *F;
    cudaGetSymbolAddress((void**)&tex1h, g_tex1h);
    cudaGetSymbolAddress((void**)&tex2h, g_tex2h);
    cudaGetSymbolAddress((void**)&vis1h, g_vis1h);
    cudaGetSymbolAddress((void**)&vis2h, g_vis2h);
    cudaGetSymbolAddress((void**)&Wqh, g_Wqh);
    cudaGetSymbolAddress((void**)&Wkh, g_Wkh);
    cudaGetSymbolAddress((void**)&Wvh, g_Wvh);
    cudaGetSymbolAddress((void**)&Woh, g_Woh);
    cudaGetSymbolAddress((void**)&W1h, g_W1h);
    cudaGetSymbolAddress((void**)&W2h, g_W2h);
    cudaGetSymbolAddress((void**)&K1h, g_K1h);
    cudaGetSymbolAddress((void**)&K2h, g_K2h);
    cudaGetSymbolAddress((void**)&V1T, g_V1T);
    cudaGetSymbolAddress((void**)&V2T, g_V2T);
    cudaGetSymbolAddress((void**)&Qh,  g_Qh);
    cudaGetSymbolAddress((void**)&S,   g_S);
    cudaGetSymbolAddress((void**)&S16, g_S16);
    cudaGetSymbolAddress((void**)&Ah,  g_Ah);
    cudaGetSymbolAddress((void**)&O,   g_O);
    cudaGetSymbolAddress((void**)&o1,  g_o1);
    cudaGetSymbolAddress((void**)&o2,  g_o2);
    cudaGetSymbolAddress((void**)&P,   g_P);
    cudaGetSymbolAddress((void**)&Ph,  g_Ph);
    cudaGetSymbolAddress((void**)&Hh,  g_Hh);
    cudaGetSymbolAddress((void**)&F,   g_F);

    static bool attr_done = false;
    if (!attr_done) {
        cudaFuncSetAttribute(hgemm_nt,
            cudaFuncAttributeMaxDynamicSharedMemorySize, SMEM_DYN);
        attr_done = true;
    }

    const dim3 blk(256);
    auto cvt = [&](const float* s, __half* d, int n) {
        int n4 = n / 4;
        cvt4<<<(n4 + 255) / 256, blk>>>(s, d, n4);
    };
    cvt(text1, tex1h, QROWS * DMODEL);
    cvt(text2, tex2h, QROWS * DMODEL);
    cvt(vis1,  vis1h, SV * DMODEL);
    cvt(vis2,  vis2h, SV * DMODEL);
    cvt(Wq, Wqh, DMODEL * DMODEL);
    cvt(Wk, Wkh, DMODEL * DMODEL);
    cvt(Wv, Wvh, DMODEL * DMODEL);
    cvt(Wo, Woh, DMODEL * DMODEL);
    cvt(W1, W1h, DFF * DMODEL);
    cvt(W2, W2h, DMODEL * DFF);

    const dim3 gKV(DMODEL / BN, SVP / BM);      // 8 x 2
    const dim3 gProj(DMODEL / BN, QROWS / BM);  // 8 x 64
    const dim3 gScore(SVP / BN, QROWS / BM);    // 2 x 64
    const dim3 gFfn1(DFF / BN, QROWS / BM);     // 32 x 64

    // ---- K/V projections (M padded to 256, real 196) ----
    hgemm_nt<<<gKV, blk, SMEM_DYN>>>(vis1h, Wkh, SVP, DMODEL, DMODEL, SV, bk,
                                     nullptr, nullptr, K1h, nullptr, 0);
    hgemm_nt<<<gKV, blk, SMEM_DYN>>>(vis1h, Wvh, SVP, DMODEL, DMODEL, SV, bv,
                                     nullptr, nullptr, nullptr, V1T, 0);
    hgemm_nt<<<gKV, blk, SMEM_DYN>>>(vis2h, Wkh, SVP, DMODEL, DMODEL, SV, bk,
                                     nullptr, nullptr, K2h, nullptr, 0);
    hgemm_nt<<<gKV, blk, SMEM_DYN>>>(vis2h, Wvh, SVP, DMODEL, DMODEL, SV, bv,
                                     nullptr, nullptr, nullptr, V2T, 0);

    // ---- Branch 1 ----
    hgemm_nt<<<gProj, blk, SMEM_DYN>>>(tex1h, Wqh, QROWS, DMODEL, DMODEL, QROWS,
                                       bq, nullptr, nullptr, Qh, nullptr, 0);
    hgemm_nt<<<gScore, blk, SMEM_DYN>>>(Qh, K1h, QROWS, SVP, DMODEL, QROWS,
                                        nullptr, nullptr, S, nullptr, nullptr, 0);
    softmax_kernel<<<QROWS, blk>>>(S, sc1, S16);
    hgemm_nt<<<gProj, blk, SMEM_DYN>>>(S16, V1T, QROWS, DMODEL, SVP, QROWS,
                                       nullptr, nullptr, nullptr, Ah, nullptr, 0);
    hgemm_nt<<<gProj, blk, SMEM_DYN>>>(Ah, Woh, QROWS, DMODEL, DMODEL, QROWS,
                                       bo, text1, O, nullptr, nullptr, 0);
    layernorm_kernel<<<QROWS, blk>>>(O, g1, be1, o1);

    // ---- Branch 2 ----
    hgemm_nt<<<gProj, blk, SMEM_DYN>>>(tex2h, Wqh, QROWS, DMODEL, DMODEL, QROWS,
                                       bq, nullptr, nullptr, Qh, nullptr, 0);
    hgemm_nt<<<gScore, blk, SMEM_DYN>>>(Qh, K2h, QROWS, SVP, DMODEL, QROWS,
                                        nullptr, nullptr, S, nullptr, nullptr, 0);
    softmax_kernel<<<QROWS, blk>>>(S, sc2, S16);
    hgemm_nt<<<gProj, blk, SMEM_DYN>>>(S16, V2T, QROWS, DMODEL, SVP, QROWS,
                                       nullptr, nullptr, nullptr, Ah, nullptr, 0);
    hgemm_nt<<<gProj, blk, SMEM_DYN>>>(Ah, Woh, QROWS, DMODEL, DMODEL, QROWS,
                                       bo, text2, O, nullptr, nullptr, 0);
    layernorm_kernel<<<QROWS, blk>>>(O, g1, be1, o2);

    // ---- Concat + MaxPool ----
    pool_kernel<<<(QROWS * DMODEL) / 256, blk>>>(o1, o2, P, Ph);

    // ---- FFN + residual + final LN ----
    hgemm_nt<<<gFfn1, blk, SMEM_DYN>>>(Ph, W1h, QROWS, DFF, DMODEL, QROWS,
                                       b1, nullptr, nullptr, Hh, nullptr, 1);
    hgemm_nt<<<gProj, blk, SMEM_DYN>>>(Hh, W2h, QROWS, DMODEL, DFF, QROWS,
                                       b2, P, F, nullptr, nullptr, 0);
    layernorm_kernel<<<QROWS, blk>>>(F, g2, be2, out);
}

// round 14
// speedup vs baseline: 2.0334x; 1.1698x over previous
#include <cuda_runtime.h>
#include <cuda_fp16.h>
#include <stdint.h>
#include <math.h>

#define DMODEL 1024
#define DFF    4096
#define SV     196
#define SVP    256
#define QROWS  (4 * 2048)   // 8192

// ---------------------------------------------------------------------------
// Scratch (device globals; allocations forbidden)
// ---------------------------------------------------------------------------
__device__ __half g_tex1h[QROWS * DMODEL];
__device__ __half g_tex2h[QROWS * DMODEL];
__device__ __half g_vis1h[SVP * DMODEL];
__device__ __half g_vis2h[SVP * DMODEL];
__device__ __half g_Wqh[DMODEL * DMODEL];
__device__ __half g_Wkh[DMODEL * DMODEL];
__device__ __half g_Wvh[DMODEL * DMODEL];
__device__ __half g_Woh[DMODEL * DMODEL];
__device__ __half g_W1h[DFF * DMODEL];
__device__ __half g_W2h[DMODEL * DFF];
__device__ __half g_K1h[SVP * DMODEL];
__device__ __half g_K2h[SVP * DMODEL];
__device__ __half g_V1T[DMODEL * SVP];
__device__ __half g_V2T[DMODEL * SVP];
__device__ __half g_Q1h[QROWS * DMODEL];
__device__ __half g_Q2h[QROWS * DMODEL];
__device__ float  g_S1 [QROWS * SVP];
__device__ float  g_S2 [QROWS * SVP];
__device__ __half g_S16a[QROWS * SVP];
__device__ __half g_S16b[QROWS * SVP];
__device__ __half g_A1h[QROWS * DMODEL];
__device__ __half g_A2h[QROWS * DMODEL];
__device__ float  g_O1 [QROWS * DMODEL];
__device__ float  g_O2 [QROWS * DMODEL];
__device__ float  g_P  [QROWS * DMODEL];
__device__ __half g_Ph [QROWS * DMODEL];
__device__ __half g_Hh [QROWS * DFF];
__device__ float  g_F  [QROWS * DMODEL];

// ---------------------------------------------------------------------------
// Helpers
// ---------------------------------------------------------------------------
#define SMEM_SWIZZLE_128B(off) ((off) ^ (((off) >> 3) & 0x70))

__device__ __forceinline__ void ldsm4(uint32_t addr,
    uint32_t& r0, uint32_t& r1, uint32_t& r2, uint32_t& r3)
{
    asm volatile("ldmatrix.sync.aligned.m8n8.x4.shared.b16 {%0,%1,%2,%3},[%4];\n"
        : "=r"(r0), "=r"(r1), "=r"(r2), "=r"(r3) : "r"(addr));
}

__device__ __forceinline__ void mma16816(float* c,
    const uint32_t* a, uint32_t b0, uint32_t b1)
{
    asm volatile(
        "mma.sync.aligned.m16n8k16.row.col.f32.f16.f16.f32 "
        "{%0,%1,%2,%3},{%4,%5,%6,%7},{%8,%9},{%0,%1,%2,%3};\n"
        : "+f"(c[0]), "+f"(c[1]), "+f"(c[2]), "+f"(c[3])
        : "r"(a[0]), "r"(a[1]), "r"(a[2]), "r"(a[3]), "r"(b0), "r"(b1));
}

__device__ __forceinline__ void cp16(uint32_t saddr, const void* gaddr, int sz)
{
    asm volatile("cp.async.cg.shared.global [%0], [%1], 16, %2;\n"
        :: "r"(saddr), "l"(gaddr), "r"(sz));
}

// ---------------------------------------------------------------------------
// Batched HMMA GEMM: per-z pointer sets; C = A[M,K] * B[N,K]^T
// CTA 128x128, 256 threads, BK=64 (SW128 swizzle), 3-stage cp.async, 2 CTA/SM.
// ---------------------------------------------------------------------------
#define BM 128
#define BN 128
#define BK 64
#define ATILE_B (BM * 128)
#define BTILE_B (BN * 128)
#define STAGE_B (ATILE_B + BTILE_B)
#define NSTAGE 3
#define SMEM_DYN (NSTAGE * STAGE_B)   // 98304

struct GemmEnt {
    const __half* A; const __half* B;
    const float* bias; const float* resid;
    float* outF; __half* outH; __half* outHT;
};
struct GemmBatch { GemmEnt e[4]; };

__global__ __launch_bounds__(256, 2) void hgemm_nt(
    GemmBatch gb, int M, int N, int K, int Mreal, int relu)
{
    extern __shared__ __align__(1024) char dsm[];

    const GemmEnt ge = gb.e[blockIdx.z];
    const __half* __restrict__ A = ge.A;
    const __half* __restrict__ B = ge.B;
    const float* bias  = ge.bias;
    const float* resid = ge.resid;
    float* outF  = ge.outF;
    __half* outH = ge.outH;
    __half* outHT = ge.outHT;

    const int tid  = threadIdx.x;
    const int lane = tid & 31;
    const int wid  = tid >> 5;
    const int warp_m = wid & 3;
    const int warp_n = wid >> 2;
    const int m0 = blockIdx.y * BM;
    const int n0 = blockIdx.x * BN;

    const uint32_t base = (uint32_t)__cvta_generic_to_shared(dsm);

    float acc[2][8][4];
#pragma unroll
    for (int i = 0; i < 2; i++)
#pragma unroll
        for (int j = 0; j < 8; j++)
#pragma unroll
            for (int r = 0; r < 4; r++) acc[i][j][r] = 0.f;

    auto issue = [&](int chunk, int stage) {
        const int k0 = chunk * BK;
        const uint32_t sA = base + stage * STAGE_B;
        const uint32_t sB = sA + ATILE_B;
#pragma unroll
        for (int j = 0; j < 4; j++) {
            int c = tid + j * 256;
            int row = c >> 3, col = c & 7;
            cp16(sA + SMEM_SWIZZLE_128B((uint32_t)(row * 128 + col * 16)),
                 A + (size_t)(m0 + row) * K + k0 + col * 8,
                 (m0 + row) < Mreal ? 16 : 0);
        }
#pragma unroll
        for (int j = 0; j < 4; j++) {
            int c = tid + j * 256;
            int row = c >> 3, col = c & 7;
            cp16(sB + SMEM_SWIZZLE_128B((uint32_t)(row * 128 + col * 16)),
                 B + (size_t)(n0 + row) * K + k0 + col * 8, 16);
        }
        asm volatile("cp.async.commit_group;\n" ::: "memory");
    };

    const int nk = K / BK;
    issue(0, 0);
    if (nk > 1) issue(1, 1);

    for (int i = 0; i < nk; i++) {
        if (i + 2 < nk) issue(i + 2, (i + 2) % NSTAGE);

        if (i + 2 < nk)
            asm volatile("cp.async.wait_group 2;\n" ::: "memory");
        else if (i + 1 < nk)
            asm volatile("cp.async.wait_group 1;\n" ::: "memory");
        else
            asm volatile("cp.async.wait_group 0;\n" ::: "memory");
        __syncthreads();

        const int st = i % NSTAGE;
        const uint32_t sA = base + st * STAGE_B;
        const uint32_t sB = sA + ATILE_B;

#pragma unroll
        for (int kk = 0; kk < 4; kk++) {
            const int kb = kk * 32;
            uint32_t a[2][4];
#pragma unroll
            for (int mi = 0; mi < 2; mi++) {
                uint32_t off = (uint32_t)(
                    (warp_m * 32 + mi * 16 + (lane & 15)) * 128 +
                    kb + ((lane >> 4) << 4));
                ldsm4(sA + SMEM_SWIZZLE_128B(off),
                      a[mi][0], a[mi][1], a[mi][2], a[mi][3]);
            }
            uint32_t b[4][4];
#pragma unroll
            for (int nj = 0; nj < 4; nj++) {
                uint32_t off = (uint32_t)(
                    (warp_n * 64 + nj * 16 + (lane & 7) + ((lane >> 4) << 3)) * 128 +
                    kb + (((lane >> 3) & 1) << 4));
                ldsm4(sB + SMEM_SWIZZLE_128B(off),
                      b[nj][0], b[nj][1], b[nj][2], b[nj][3]);
            }
#pragma unroll
            for (int mi = 0; mi < 2; mi++)
#pragma unroll
                for (int nf = 0; nf < 8; nf++) {
                    const int nj = nf >> 1;
                    uint32_t b0 = (nf & 1) ? b[nj][2] : b[nj][0];
                    uint32_t b1 = (nf & 1) ? b[nj][3] : b[nj][1];
                    mma16816(acc[mi][nf], a[mi], b0, b1);
                }
        }
        __syncthreads();
    }

#pragma unroll
    for (int mi = 0; mi < 2; mi++)
#pragma unroll
        for (int nf = 0; nf < 8; nf++)
#pragma unroll
            for (int r = 0; r < 4; r++) {
                int m = m0 + warp_m * 32 + mi * 16 + (lane >> 2) + ((r >= 2) ? 8 : 0);
                int n = n0 + warp_n * 64 + nf * 8 + (lane & 3) * 2 + (r & 1);
                float v = acc[mi][nf][r];
                if (bias)  v += bias[n];
                if (resid) v += resid[(size_t)m * N + n];
                if (relu)  v = fmaxf(v, 0.f);
                if (m >= Mreal) v = 0.f;
                if (outF)  outF[(size_t)m * N + n] = v;
                if (outH)  outH[(size_t)m * N + n] = __float2half_rn(v);
                if (outHT) outHT[(size_t)n * SVP + m] = __float2half_rn(v);
            }
}

// ---------------------------------------------------------------------------
// One-shot f32->f16 conversion of all 10 buffers (compile-time segment table)
// ---------------------------------------------------------------------------
#define T_N4  (QROWS * DMODEL / 4)      // 2097152
#define V_N4  (SV * DMODEL / 4)         // 50176
#define W_N4  (DMODEL * DMODEL / 4)     // 262144
#define W1_N4 (DFF * DMODEL / 4)        // 1048576
#define CP0 0
#define CP1 (CP0 + T_N4)
#define CP2 (CP1 + T_N4)
#define CP3 (CP2 + V_N4)
#define CP4 (CP3 + V_N4)
#define CP5 (CP4 + W_N4)
#define CP6 (CP5 + W_N4)
#define CP7 (CP6 + W_N4)
#define CP8 (CP7 + W_N4)
#define CP9 (CP8 + W1_N4)
#define CP10 (CP9 + W1_N4)              // 7440384 total n4
#define CVT_BLOCKS (CP10 / 256)         // 29064

struct CvtArgs {
    const float* s[10];
    __half* d[10];
};

__global__ __launch_bounds__(256) void cvt_all(CvtArgs a)
{
    int idx = blockIdx.x * 256 + threadIdx.x;
    int seg, base;
    if      (idx < CP1) { seg = 0; base = CP0; }
    else if (idx < CP2) { seg = 1; base = CP1; }
    else if (idx < CP3) { seg = 2; base = CP2; }
    else if (idx < CP4) { seg = 3; base = CP3; }
    else if (idx < CP5) { seg = 4; base = CP4; }
    else if (idx < CP6) { seg = 5; base = CP5; }
    else if (idx < CP7) { seg = 6; base = CP6; }
    else if (idx < CP8) { seg = 7; base = CP7; }
    else if (idx < CP9) { seg = 8; base = CP8; }
    else                { seg = 9; base = CP9; }
    int i = idx - base;
    float4 v = ((const float4*)a.s[seg])[i];
    __half2* dp = (__half2*)a.d[seg];
    dp[2 * i + 0] = __floats2half2_rn(v.x, v.y);
    dp[2 * i + 1] = __floats2half2_rn(v.z, v.w);
}

// ---------------------------------------------------------------------------
// Batched softmax over Sv=196 (blockIdx.y = branch)
// ---------------------------------------------------------------------------
__global__ __launch_bounds__(256) void softmax_kernel(
    const float* __restrict__ S1, const float* __restrict__ sc1, __half* __restrict__ D1,
    const float* __restrict__ S2, const float* __restrict__ sc2, __half* __restrict__ D2)
{
    const float* S = blockIdx.y ? S2 : S1;
    const float* score = blockIdx.y ? sc2 : sc1;
    __half* S16 = blockIdx.y ? D2 : D1;

    const int r = blockIdx.x;
    const int t = threadIdx.x;
    __shared__ float red[256];

    float myval = 0.f, v = -1e30f;
    if (t < SV) {
        myval = (S[(size_t)r * SVP + t] + score[(size_t)r * SV + t]) * 0.125f;
        v = myval;
    }
    red[t] = v;
    __syncthreads();
    for (int s = 128; s > 0; s >>= 1) {
        if (t < s) red[t] = fmaxf(red[t], red[t + s]);
        __syncthreads();
    }
    const float mx = red[0];
    __syncthreads();
    float e = (t < SV) ? __expf(myval - mx) : 0.f;
    red[t] = e;
    __syncthreads();
    for (int s = 128; s > 0; s >>= 1) {
        if (t < s) red[t] += red[t + s];
        __syncthreads();
    }
    const float inv = 1.f / red[0];
    S16[(size_t)r * SVP + t] = __float2half_rn((t < SV) ? e * inv : 0.f);
}

// ---------------------------------------------------------------------------
// Fused LN(O1) + LN(O2) + concat-maxpool -> P (f32), Ph (f16)
// ---------------------------------------------------------------------------
__global__ __launch_bounds__(256) void ln_pool_kernel(
    const float* __restrict__ O1, const float* __restrict__ O2,
    const float* __restrict__ g, const float* __restrict__ b,
    float* __restrict__ P, __half* __restrict__ Ph)
{
    const int r = blockIdx.x;
    const int t = threadIdx.x;
    __shared__ float row1[DMODEL], row2[DMODEL];
    __shared__ float rs1[256], rss1[256], rs2[256], rss2[256];

    float v1[4], v2[4];
    float s1 = 0.f, ss1 = 0.f, s2 = 0.f, ss2 = 0.f;
#pragma unroll
    for (int i = 0; i < 4; i++) {
        int c = t + i * 256;
        float a = O1[(size_t)r * DMODEL + c];
        float d = O2[(size_t)r * DMODEL + c];
        v1[i] = a; s1 += a; ss1 += a * a;
        v2[i] = d; s2 += d; ss2 += d * d;
    }
    rs1[t] = s1; rss1[t] = ss1; rs2[t] = s2; rss2[t] = ss2;
    __syncthreads();
    for (int k = 128; k > 0; k >>= 1) {
        if (t < k) {
            rs1[t] += rs1[t + k]; rss1[t] += rss1[t + k];
            rs2[t] += rs2[t + k]; rss2[t] += rss2[t + k];
        }
        __syncthreads();
    }
    const float mu1 = rs1[0] * (1.f / DMODEL);
    const float var1 = rss1[0] * (1.f / DMODEL) - mu1 * mu1;
    const float inv1 = rsqrtf(var1 + 1e-6f);
    const float mu2 = rs2[0] * (1.f / DMODEL);
    const float var2 = rss2[0] * (1.f / DMODEL) - mu2 * mu2;
    const float inv2 = rsqrtf(var2 + 1e-6f);
#pragma unroll
    for (int i = 0; i < 4; i++) {
        int c = t + i * 256;
        row1[c] = (v1[i] - mu1) * inv1 * g[c] + b[c];
        row2[c] = (v2[i] - mu2) * inv2 * g[c] + b[c];
    }
    __syncthreads();
#pragma unroll
    for (int i = 0; i < 4; i++) {
        int c = t + i * 256;
        float p = (c < 512) ? fmaxf(row1[2 * c], row1[2 * c + 1])
                            : fmaxf(row2[2 * c - DMODEL], row2[2 * c - DMODEL + 1]);
        P[(size_t)r * DMODEL + c] = p;
        Ph[(size_t)r * DMODEL + c] = __float2half_rn(p);
    }
}

// ---------------------------------------------------------------------------
// LayerNorm over D=1024
// ---------------------------------------------------------------------------
__global__ __launch_bounds__(256) void layernorm_kernel(
    const float* __restrict__ X, const float* __restrict__ g,
    const float* __restrict__ b, float* __restrict__ Y)
{
    const int r = blockIdx.x;
    const int t = threadIdx.x;
    const float* x = X + (size_t)r * DMODEL;

    float vals[4];
    float s = 0.f, ss = 0.f;
#pragma unroll
    for (int i = 0; i < 4; i++) {
        float v = x[t + i * 256];
        vals[i] = v;
        s += v;
        ss += v * v;
    }
    __shared__ float rs[256], rss[256];
    rs[t] = s; rss[t] = ss;
    __syncthreads();
    for (int k = 128; k > 0; k >>= 1) {
        if (t < k) { rs[t] += rs[t + k]; rss[t] += rss[t + k]; }
        __syncthreads();
    }
    const float mu = rs[0] * (1.f / DMODEL);
    const float var = rss[0] * (1.f / DMODEL) - mu * mu;
    const float inv = rsqrtf(var + 1e-6f);
#pragma unroll
    for (int i = 0; i < 4; i++) {
        int c = t + i * 256;
        Y[(size_t)r * DMODEL + c] = (vals[i] - mu) * inv * g[c] + b[c];
    }
}

// ---------------------------------------------------------------------------
// Host orchestration
// ---------------------------------------------------------------------------
extern "C" void kernel_launch(void* const* d_in, const int* in_sizes, int n_in,
                              void* d_out, int out_size)
{
    const float* text1 = (const float*)d_in[0];
    const float* vis1  = (const float*)d_in[1];
    const float* sc1   = (const float*)d_in[2];
    const float* text2 = (const float*)d_in[3];
    const float* vis2  = (const float*)d_in[4];
    const float* sc2   = (const float*)d_in[5];
    const float* Wq = (const float*)d_in[6],  *bq = (const float*)d_in[7];
    const float* Wk = (const float*)d_in[8],  *bk = (const float*)d_in[9];
    const float* Wv = (const float*)d_in[10], *bv = (const float*)d_in[11];
    const float* Wo = (const float*)d_in[12], *bo = (const float*)d_in[13];
    const float* W1 = (const float*)d_in[14], *b1 = (const float*)d_in[15];
    const float* W2 = (const float*)d_in[16], *b2 = (const float*)d_in[17];
    const float* g1 = (const float*)d_in[18], *be1 = (const float*)d_in[19];
    const float* g2 = (const float*)d_in[20], *be2 = (const float*)d_in[21];
    float* out = (float*)d_out;

    __half *tex1h, *tex2h, *vis1h, *vis2h, *Wqh, *Wkh, *Wvh, *Woh, *W1h, *W2h;
    __half *K1h, *K2h, *V1T, *V2T, *Q1h, *Q2h, *S16a, *S16b, *A1h, *A2h, *Ph, *Hh;
    float *S1, *S2, *O1, *O2, *P, *F;
    cudaGetSymbolAddress((void**)&tex1h, g_tex1h);
    cudaGetSymbolAddress((void**)&tex2h, g_tex2h);
    cudaGetSymbolAddress((void**)&vis1h, g_vis1h);
    cudaGetSymbolAddress((void**)&vis2h, g_vis2h);
    cudaGetSymbolAddress((void**)&Wqh, g_Wqh);
    cudaGetSymbolAddress((void**)&Wkh, g_Wkh);
    cudaGetSymbolAddress((void**)&Wvh, g_Wvh);
    cudaGetSymbolAddress((void**)&Woh, g_Woh);
    cudaGetSymbolAddress((void**)&W1h, g_W1h);
    cudaGetSymbolAddress((void**)&W2h, g_W2h);
    cudaGetSymbolAddress((void**)&K1h, g_K1h);
    cudaGetSymbolAddress((void**)&K2h, g_K2h);
    cudaGetSymbolAddress((void**)&V1T, g_V1T);
    cudaGetSymbolAddress((void**)&V2T, g_V2T);
    cudaGetSymbolAddress((void**)&Q1h, g_Q1h);
    cudaGetSymbolAddress((void**)&Q2h, g_Q2h);
    cudaGetSymbolAddress((void**)&S1,  g_S1);
    cudaGetSymbolAddress((void**)&S2,  g_S2);
    cudaGetSymbolAddress((void**)&S16a, g_S16a);
    cudaGetSymbolAddress((void**)&S16b, g_S16b);
    cudaGetSymbolAddress((void**)&A1h, g_A1h);
    cudaGetSymbolAddress((void**)&A2h, g_A2h);
    cudaGetSymbolAddress((void**)&O1,  g_O1);
    cudaGetSymbolAddress((void**)&O2,  g_O2);
    cudaGetSymbolAddress((void**)&P,   g_P);
    cudaGetSymbolAddress((void**)&Ph,  g_Ph);
    cudaGetSymbolAddress((void**)&Hh,  g_Hh);
    cudaGetSymbolAddress((void**)&F,   g_F);

    static bool attr_done = false;
    if (!attr_done) {
        cudaFuncSetAttribute(hgemm_nt,
            cudaFuncAttributeMaxDynamicSharedMemorySize, SMEM_DYN);
        attr_done = true;
    }

    const dim3 blk(256);

    // ---- one-shot conversions ----
    CvtArgs ca;
    ca.s[0] = text1; ca.d[0] = tex1h;
    ca.s[1] = text2; ca.d[1] = tex2h;
    ca.s[2] = vis1;  ca.d[2] = vis1h;
    ca.s[3] = vis2;  ca.d[3] = vis2h;
    ca.s[4] = Wq;    ca.d[4] = Wqh;
    ca.s[5] = Wk;    ca.d[5] = Wkh;
    ca.s[6] = Wv;    ca.d[6] = Wvh;
    ca.s[7] = Wo;    ca.d[7] = Woh;
    ca.s[8] = W1;    ca.d[8] = W1h;
    ca.s[9] = W2;    ca.d[9] = W2h;
    cvt_all<<<CVT_BLOCKS, blk>>>(ca);

    GemmBatch gb;
    auto E = [](const __half* A, const __half* B, const float* bias,
                const float* resid, float* oF, __half* oH, __half* oHT) {
        GemmEnt e; e.A = A; e.B = B; e.bias = bias; e.resid = resid;
        e.outF = oF; e.outH = oH; e.outHT = oHT; return e;
    };

    // ---- K/V projections, all 4 in one launch (z=0..3) ----
    gb.e[0] = E(vis1h, Wkh, bk, nullptr, nullptr, K1h, nullptr);
    gb.e[1] = E(vis1h, Wvh, bv, nullptr, nullptr, nullptr, V1T);
    gb.e[2] = E(vis2h, Wkh, bk, nullptr, nullptr, K2h, nullptr);
    gb.e[3] = E(vis2h, Wvh, bv, nullptr, nullptr, nullptr, V2T);
    hgemm_nt<<<dim3(DMODEL / BN, SVP / BM, 4), blk, SMEM_DYN>>>(
        gb, SVP, DMODEL, DMODEL, SV, 0);

    // ---- Q projections (both branches) ----
    gb.e[0] = E(tex1h, Wqh, bq, nullptr, nullptr, Q1h, nullptr);
    gb.e[1] = E(tex2h, Wqh, bq, nullptr, nullptr, Q2h, nullptr);
    hgemm_nt<<<dim3(DMODEL / BN, QROWS / BM, 2), blk, SMEM_DYN>>>(
        gb, QROWS, DMODEL, DMODEL, QROWS, 0);

    // ---- scores (both branches) ----
    gb.e[0] = E(Q1h, K1h, nullptr, nullptr, S1, nullptr, nullptr);
    gb.e[1] = E(Q2h, K2h, nullptr, nullptr, S2, nullptr, nullptr);
    hgemm_nt<<<dim3(SVP / BN, QROWS / BM, 2), blk, SMEM_DYN>>>(
        gb, QROWS, SVP, DMODEL, QROWS, 0);

    // ---- softmax (both branches) ----
    softmax_kernel<<<dim3(QROWS, 2), blk>>>(S1, sc1, S16a, S2, sc2, S16b);

    // ---- S·V (both branches) ----
    gb.e[0] = E(S16a, V1T, nullptr, nullptr, nullptr, A1h, nullptr);
    gb.e[1] = E(S16b, V2T, nullptr, nullptr, nullptr, A2h, nullptr);
    hgemm_nt<<<dim3(DMODEL / BN, QROWS / BM, 2), blk, SMEM_DYN>>>(
        gb, QROWS, DMODEL, SVP, QROWS, 0);

    // ---- O projections + residual (both branches) ----
    gb.e[0] = E(A1h, Woh, bo, text1, O1, nullptr, nullptr);
    gb.e[1] = E(A2h, Woh, bo, text2, O2, nullptr, nullptr);
    hgemm_nt<<<dim3(DMODEL / BN, QROWS / BM, 2), blk, SMEM_DYN>>>(
        gb, QROWS, DMODEL, DMODEL, QROWS, 0);

    // ---- fused LN + LN + concat-maxpool ----
    ln_pool_kernel<<<QROWS, blk>>>(O1, O2, g1, be1, P, Ph);

    // ---- FFN1 (relu) ----
    gb.e[0] = E(Ph, W1h, b1, nullptr, nullptr, Hh, nullptr);
    hgemm_nt<<<dim3(DFF / BN, QROWS / BM, 1), blk, SMEM_DYN>>>(
        gb, QROWS, DFF, DMODEL, QROWS, 1);

    // ---- FFN2 + residual ----
    gb.e[0] = E(Hh, W2h, b2, P, F, nullptr, nullptr);
    hgemm_nt<<<dim3(DMODEL / BN, QROWS / BM, 1), blk, SMEM_DYN>>>(
        gb, QROWS, DMODEL, DFF, QROWS, 0);

    // ---- final LN ----
    layernorm_kernel<<<QROWS, blk>>>(F, g2, be2, out);
}

// round 15
// speedup vs baseline: 2.5671x; 1.2625x over previous
#include <cuda_runtime.h>
#include <cuda_fp16.h>
#include <stdint.h>
#include <math.h>

#define DMODEL 1024
#define DFF    4096
#define SV     196
#define SVP    256
#define QROWS  (4 * 2048)   // 8192

// ---------------------------------------------------------------------------
// Scratch (device globals; allocations forbidden)
// ---------------------------------------------------------------------------
__device__ __half g_tex1h[QROWS * DMODEL];
__device__ __half g_tex2h[QROWS * DMODEL];
__device__ __half g_vis1h[SVP * DMODEL];
__device__ __half g_vis2h[SVP * DMODEL];
__device__ __half g_WqTh[DMODEL * DMODEL];   // Wq transposed
__device__ __half g_Wkh[DMODEL * DMODEL];
__device__ __half g_Wvh[DMODEL * DMODEL];
__device__ __half g_Woh[DMODEL * DMODEL];
__device__ __half g_W1h[DFF * DMODEL];
__device__ __half g_W2h[DMODEL * DFF];
__device__ __half g_K1h[SVP * DMODEL];
__device__ __half g_K2h[SVP * DMODEL];
__device__ __half g_V1h[SVP * DMODEL];
__device__ __half g_V2h[SVP * DMODEL];
__device__ __half g_Kt1h[SVP * DMODEL];      // K~ = K @ Wq
__device__ __half g_Kt2h[SVP * DMODEL];
__device__ __half g_V1Tp[DMODEL * SVP];      // (V @ Wo^T)^T
__device__ __half g_V2Tp[DMODEL * SVP];
__device__ float  g_cvec[2 * SVP];           // dot(bq, K[k]) per branch
__device__ float  g_S1 [QROWS * SVP];
__device__ float  g_S2 [QROWS * SVP];
__device__ __half g_S16a[QROWS * SVP];
__device__ __half g_S16b[QROWS * SVP];
__device__ float  g_O1 [QROWS * DMODEL];
__device__ float  g_O2 [QROWS * DMODEL];
__device__ float  g_P  [QROWS * DMODEL];
__device__ __half g_Ph [QROWS * DMODEL];
__device__ __half g_Hh [QROWS * DFF];
__device__ float  g_F  [QROWS * DMODEL];

// ---------------------------------------------------------------------------
// Helpers
// ---------------------------------------------------------------------------
#define SMEM_SWIZZLE_128B(off) ((off) ^ (((off) >> 3) & 0x70))

__device__ __forceinline__ void ldsm4(uint32_t addr,
    uint32_t& r0, uint32_t& r1, uint32_t& r2, uint32_t& r3)
{
    asm volatile("ldmatrix.sync.aligned.m8n8.x4.shared.b16 {%0,%1,%2,%3},[%4];\n"
        : "=r"(r0), "=r"(r1), "=r"(r2), "=r"(r3) : "r"(addr));
}

__device__ __forceinline__ void mma16816(float* c,
    const uint32_t* a, uint32_t b0, uint32_t b1)
{
    asm volatile(
        "mma.sync.aligned.m16n8k16.row.col.f32.f16.f16.f32 "
        "{%0,%1,%2,%3},{%4,%5,%6,%7},{%8,%9},{%0,%1,%2,%3};\n"
        : "+f"(c[0]), "+f"(c[1]), "+f"(c[2]), "+f"(c[3])
        : "r"(a[0]), "r"(a[1]), "r"(a[2]), "r"(a[3]), "r"(b0), "r"(b1));
}

__device__ __forceinline__ void cp16(uint32_t saddr, const void* gaddr, int sz)
{
    asm volatile("cp.async.cg.shared.global [%0], [%1], 16, %2;\n"
        :: "r"(saddr), "l"(gaddr), "r"(sz));
}

// ---------------------------------------------------------------------------
// Batched HMMA GEMM: per-z pointer sets; C = A[M,K] * B[N,K]^T
// CTA 128x128, 256 threads, BK=64 (SW128 swizzle), 3-stage cp.async, 2 CTA/SM.
// ---------------------------------------------------------------------------
#define BM 128
#define BN 128
#define BK 64
#define ATILE_B (BM * 128)
#define BTILE_B (BN * 128)
#define STAGE_B (ATILE_B + BTILE_B)
#define NSTAGE 3
#define SMEM_DYN (NSTAGE * STAGE_B)   // 98304

struct GemmEnt {
    const __half* A; const __half* B;
    const float* bias; const float* resid;
    float* outF; __half* outH; __half* outHT;
};
struct GemmBatch { GemmEnt e[4]; };

__global__ __launch_bounds__(256, 2) void hgemm_nt(
    GemmBatch gb, int M, int N, int K, int Mreal, int relu)
{
    extern __shared__ __align__(1024) char dsm[];

    const GemmEnt ge = gb.e[blockIdx.z];
    const __half* __restrict__ A = ge.A;
    const __half* __restrict__ B = ge.B;
    const float* bias  = ge.bias;
    const float* resid = ge.resid;
    float* outF  = ge.outF;
    __half* outH = ge.outH;
    __half* outHT = ge.outHT;

    const int tid  = threadIdx.x;
    const int lane = tid & 31;
    const int wid  = tid >> 5;
    const int warp_m = wid & 3;
    const int warp_n = wid >> 2;
    const int m0 = blockIdx.y * BM;
    const int n0 = blockIdx.x * BN;

    const uint32_t base = (uint32_t)__cvta_generic_to_shared(dsm);

    float acc[2][8][4];
#pragma unroll
    for (int i = 0; i < 2; i++)
#pragma unroll
        for (int j = 0; j < 8; j++)
#pragma unroll
            for (int r = 0; r < 4; r++) acc[i][j][r] = 0.f;

    auto issue = [&](int chunk, int stage) {
        const int k0 = chunk * BK;
        const uint32_t sA = base + stage * STAGE_B;
        const uint32_t sB = sA + ATILE_B;
#pragma unroll
        for (int j = 0; j < 4; j++) {
            int c = tid + j * 256;
            int row = c >> 3, col = c & 7;
            cp16(sA + SMEM_SWIZZLE_128B((uint32_t)(row * 128 + col * 16)),
                 A + (size_t)(m0 + row) * K + k0 + col * 8,
                 (m0 + row) < Mreal ? 16 : 0);
        }
#pragma unroll
        for (int j = 0; j < 4; j++) {
            int c = tid + j * 256;
            int row = c >> 3, col = c & 7;
            cp16(sB + SMEM_SWIZZLE_128B((uint32_t)(row * 128 + col * 16)),
                 B + (size_t)(n0 + row) * K + k0 + col * 8, 16);
        }
        asm volatile("cp.async.commit_group;\n" ::: "memory");
    };

    const int nk = K / BK;
    issue(0, 0);
    if (nk > 1) issue(1, 1);

    for (int i = 0; i < nk; i++) {
        if (i + 2 < nk) issue(i + 2, (i + 2) % NSTAGE);

        if (i + 2 < nk)
            asm volatile("cp.async.wait_group 2;\n" ::: "memory");
        else if (i + 1 < nk)
            asm volatile("cp.async.wait_group 1;\n" ::: "memory");
        else
            asm volatile("cp.async.wait_group 0;\n" ::: "memory");
        __syncthreads();

        const int st = i % NSTAGE;
        const uint32_t sA = base + st * STAGE_B;
        const uint32_t sB = sA + ATILE_B;

#pragma unroll
        for (int kk = 0; kk < 4; kk++) {
            const int kb = kk * 32;
            uint32_t a[2][4];
#pragma unroll
            for (int mi = 0; mi < 2; mi++) {
                uint32_t off = (uint32_t)(
                    (warp_m * 32 + mi * 16 + (lane & 15)) * 128 +
                    kb + ((lane >> 4) << 4));
                ldsm4(sA + SMEM_SWIZZLE_128B(off),
                      a[mi][0], a[mi][1], a[mi][2], a[mi][3]);
            }
            uint32_t b[4][4];
#pragma unroll
            for (int nj = 0; nj < 4; nj++) {
                uint32_t off = (uint32_t)(
                    (warp_n * 64 + nj * 16 + (lane & 7) + ((lane >> 4) << 3)) * 128 +
                    kb + (((lane >> 3) & 1) << 4));
                ldsm4(sB + SMEM_SWIZZLE_128B(off),
                      b[nj][0], b[nj][1], b[nj][2], b[nj][3]);
            }
#pragma unroll
            for (int mi = 0; mi < 2; mi++)
#pragma unroll
                for (int nf = 0; nf < 8; nf++) {
                    const int nj = nf >> 1;
                    uint32_t b0 = (nf & 1) ? b[nj][2] : b[nj][0];
                    uint32_t b1 = (nf & 1) ? b[nj][3] : b[nj][1];
                    mma16816(acc[mi][nf], a[mi], b0, b1);
                }
        }
        __syncthreads();
    }

#pragma unroll
    for (int mi = 0; mi < 2; mi++)
#pragma unroll
        for (int nf = 0; nf < 8; nf++)
#pragma unroll
            for (int r = 0; r < 4; r++) {
                int m = m0 + warp_m * 32 + mi * 16 + (lane >> 2) + ((r >= 2) ? 8 : 0);
                int n = n0 + warp_n * 64 + nf * 8 + (lane & 3) * 2 + (r & 1);
                float v = acc[mi][nf][r];
                if (bias)  v += bias[n];
                if (resid) v += resid[(size_t)m * N + n];
                if (relu)  v = fmaxf(v, 0.f);
                if (m >= Mreal) v = 0.f;
                if (outF)  outF[(size_t)m * N + n] = v;
                if (outH)  outH[(size_t)m * N + n] = __float2half_rn(v);
                if (outHT) outHT[(size_t)n * SVP + m] = __float2half_rn(v);
            }
}

// ---------------------------------------------------------------------------
// One-shot f32->f16 conversion; seg 4 (Wq) is written TRANSPOSED.
// ---------------------------------------------------------------------------
#define T_N4  (QROWS * DMODEL / 4)
#define V_N4  (SV * DMODEL / 4)
#define W_N4  (DMODEL * DMODEL / 4)
#define W1_N4 (DFF * DMODEL / 4)
#define CP0 0
#define CP1 (CP0 + T_N4)
#define CP2 (CP1 + T_N4)
#define CP3 (CP2 + V_N4)
#define CP4 (CP3 + V_N4)
#define CP5 (CP4 + W_N4)
#define CP6 (CP5 + W_N4)
#define CP7 (CP6 + W_N4)
#define CP8 (CP7 + W_N4)
#define CP9 (CP8 + W1_N4)
#define CP10 (CP9 + W1_N4)
#define CVT_BLOCKS (CP10 / 256)

struct CvtArgs {
    const float* s[10];
    __half* d[10];
};

__global__ __launch_bounds__(256) void cvt_all(CvtArgs a)
{
    int idx = blockIdx.x * 256 + threadIdx.x;
    int seg, base;
    if      (idx < CP1) { seg = 0; base = CP0; }
    else if (idx < CP2) { seg = 1; base = CP1; }
    else if (idx < CP3) { seg = 2; base = CP2; }
    else if (idx < CP4) { seg = 3; base = CP3; }
    else if (idx < CP5) { seg = 4; base = CP4; }
    else if (idx < CP6) { seg = 5; base = CP5; }
    else if (idx < CP7) { seg = 6; base = CP6; }
    else if (idx < CP8) { seg = 7; base = CP7; }
    else if (idx < CP9) { seg = 8; base = CP8; }
    else                { seg = 9; base = CP9; }
    int i = idx - base;
    float4 v = ((const float4*)a.s[seg])[i];
    if (seg == 4) {
        // Wq -> WqT (transposed element-wise)
        int row = i >> 8;              // source row (0..1023)
        int col = (i & 255) * 4;       // source col base
        __half* d = a.d[4];
        d[(size_t)(col + 0) * DMODEL + row] = __float2half_rn(v.x);
        d[(size_t)(col + 1) * DMODEL + row] = __float2half_rn(v.y);
        d[(size_t)(col + 2) * DMODEL + row] = __float2half_rn(v.z);
        d[(size_t)(col + 3) * DMODEL + row] = __float2half_rn(v.w);
    } else {
        __half2* dp = (__half2*)a.d[seg];
        dp[2 * i + 0] = __floats2half2_rn(v.x, v.y);
        dp[2 * i + 1] = __floats2half2_rn(v.z, v.w);
    }
}

// ---------------------------------------------------------------------------
// cvec[br][k] = dot(bq, K_br[k])  (K fp16 rows, bq f32)
// ---------------------------------------------------------------------------
__global__ __launch_bounds__(256) void cvec_kernel(
    const __half* __restrict__ K1, const __half* __restrict__ K2,
    const float* __restrict__ bq, float* __restrict__ cv)
{
    const int k = blockIdx.x;
    const __half* K = blockIdx.y ? K2 : K1;
    const int t = threadIdx.x;
    float s = 0.f;
#pragma unroll
    for (int i = 0; i < 4; i++) {
        int c = t + i * 256;
        s += bq[c] * __half2float(K[(size_t)k * DMODEL + c]);
    }
    __shared__ float red[256];
    red[t] = s;
    __syncthreads();
    for (int st = 128; st > 0; st >>= 1) {
        if (t < st) red[t] += red[t + st];
        __syncthreads();
    }
    if (t == 0) cv[blockIdx.y * SVP + k] = red[0];
}

// ---------------------------------------------------------------------------
// Batched softmax over Sv=196 (adds cvec + score matrix)
// ---------------------------------------------------------------------------
__global__ __launch_bounds__(256) void softmax_kernel(
    const float* __restrict__ S1, const float* __restrict__ sc1, __half* __restrict__ D1,
    const float* __restrict__ S2, const float* __restrict__ sc2, __half* __restrict__ D2,
    const float* __restrict__ cv)
{
    const float* S = blockIdx.y ? S2 : S1;
    const float* score = blockIdx.y ? sc2 : sc1;
    __half* S16 = blockIdx.y ? D2 : D1;
    const float* cvb = cv + blockIdx.y * SVP;

    const int r = blockIdx.x;
    const int t = threadIdx.x;
    __shared__ float red[256];

    float myval = 0.f, v = -1e30f;
    if (t < SV) {
        myval = (S[(size_t)r * SVP + t] + cvb[t] + score[(size_t)r * SV + t]) * 0.125f;
        v = myval;
    }
    red[t] = v;
    __syncthreads();
    for (int s = 128; s > 0; s >>= 1) {
        if (t < s) red[t] = fmaxf(red[t], red[t + s]);
        __syncthreads();
    }
    const float mx = red[0];
    __syncthreads();
    float e = (t < SV) ? __expf(myval - mx) : 0.f;
    red[t] = e;
    __syncthreads();
    for (int s = 128; s > 0; s >>= 1) {
        if (t < s) red[t] += red[t + s];
        __syncthreads();
    }
    const float inv = 1.f / red[0];
    S16[(size_t)r * SVP + t] = __float2half_rn((t < SV) ? e * inv : 0.f);
}

// ---------------------------------------------------------------------------
// Fused LN(O1) + LN(O2) + concat-maxpool -> P (f32), Ph (f16)
// ---------------------------------------------------------------------------
__global__ __launch_bounds__(256) void ln_pool_kernel(
    const float* __restrict__ O1, const float* __restrict__ O2,
    const float* __restrict__ g, const float* __restrict__ b,
    float* __restrict__ P, __half* __restrict__ Ph)
{
    const int r = blockIdx.x;
    const int t = threadIdx.x;
    __shared__ float row1[DMODEL], row2[DMODEL];
    __shared__ float rs1[256], rss1[256], rs2[256], rss2[256];

    float v1[4], v2[4];
    float s1 = 0.f, ss1 = 0.f, s2 = 0.f, ss2 = 0.f;
#pragma unroll
    for (int i = 0; i < 4; i++) {
        int c = t + i * 256;
        float a = O1[(size_t)r * DMODEL + c];
        float d = O2[(size_t)r * DMODEL + c];
        v1[i] = a; s1 += a; ss1 += a * a;
        v2[i] = d; s2 += d; ss2 += d * d;
    }
    rs1[t] = s1; rss1[t] = ss1; rs2[t] = s2; rss2[t] = ss2;
    __syncthreads();
    for (int k = 128; k > 0; k >>= 1) {
        if (t < k) {
            rs1[t] += rs1[t + k]; rss1[t] += rss1[t + k];
            rs2[t] += rs2[t + k]; rss2[t] += rss2[t + k];
        }
        __syncthreads();
    }
    const float mu1 = rs1[0] * (1.f / DMODEL);
    const float var1 = rss1[0] * (1.f / DMODEL) - mu1 * mu1;
    const float inv1 = rsqrtf(var1 + 1e-6f);
    const float mu2 = rs2[0] * (1.f / DMODEL);
    const float var2 = rss2[0] * (1.f / DMODEL) - mu2 * mu2;
    const float inv2 = rsqrtf(var2 + 1e-6f);
#pragma unroll
    for (int i = 0; i < 4; i++) {
        int c = t + i * 256;
        row1[c] = (v1[i] - mu1) * inv1 * g[c] + b[c];
        row2[c] = (v2[i] - mu2) * inv2 * g[c] + b[c];
    }
    __syncthreads();
#pragma unroll
    for (int i = 0; i < 4; i++) {
        int c = t + i * 256;
        float p = (c < 512) ? fmaxf(row1[2 * c], row1[2 * c + 1])
                            : fmaxf(row2[2 * c - DMODEL], row2[2 * c - DMODEL + 1]);
        P[(size_t)r * DMODEL + c] = p;
        Ph[(size_t)r * DMODEL + c] = __float2half_rn(p);
    }
}

// ---------------------------------------------------------------------------
// LayerNorm over D=1024
// ---------------------------------------------------------------------------
__global__ __launch_bounds__(256) void layernorm_kernel(
    const float* __restrict__ X, const float* __restrict__ g,
    const float* __restrict__ b, float* __restrict__ Y)
{
    const int r = blockIdx.x;
    const int t = threadIdx.x;
    const float* x = X + (size_t)r * DMODEL;

    float vals[4];
    float s = 0.f, ss = 0.f;
#pragma unroll
    for (int i = 0; i < 4; i++) {
        float v = x[t + i * 256];
        vals[i] = v;
        s += v;
        ss += v * v;
    }
    __shared__ float rs[256], rss[256];
    rs[t] = s; rss[t] = ss;
    __syncthreads();
    for (int k = 128; k > 0; k >>= 1) {
        if (t < k) { rs[t] += rs[t + k]; rss[t] += rss[t + k]; }
        __syncthreads();
    }
    const float mu = rs[0] * (1.f / DMODEL);
    const float var = rss[0] * (1.f / DMODEL) - mu * mu;
    const float inv = rsqrtf(var + 1e-6f);
#pragma unroll
    for (int i = 0; i < 4; i++) {
        int c = t + i * 256;
        Y[(size_t)r * DMODEL + c] = (vals[i] - mu) * inv * g[c] + b[c];
    }
}

// ---------------------------------------------------------------------------
// Host orchestration
// ---------------------------------------------------------------------------
extern "C" void kernel_launch(void* const* d_in, const int* in_sizes, int n_in,
                              void* d_out, int out_size)
{
    const float* text1 = (const float*)d_in[0];
    const float* vis1  = (const float*)d_in[1];
    const float* sc1   = (const float*)d_in[2];
    const float* text2 = (const float*)d_in[3];
    const float* vis2  = (const float*)d_in[4];
    const float* sc2   = (const float*)d_in[5];
    const float* Wq = (const float*)d_in[6],  *bq = (const float*)d_in[7];
    const float* Wk = (const float*)d_in[8],  *bk = (const float*)d_in[9];
    const float* Wv = (const float*)d_in[10], *bv = (const float*)d_in[11];
    const float* Wo = (const float*)d_in[12], *bo = (const float*)d_in[13];
    const float* W1 = (const float*)d_in[14], *b1 = (const float*)d_in[15];
    const float* W2 = (const float*)d_in[16], *b2 = (const float*)d_in[17];
    const float* g1 = (const float*)d_in[18], *be1 = (const float*)d_in[19];
    const float* g2 = (const float*)d_in[20], *be2 = (const float*)d_in[21];
    float* out = (float*)d_out;

    __half *tex1h, *tex2h, *vis1h, *vis2h, *WqTh, *Wkh, *Wvh, *Woh, *W1h, *W2h;
    __half *K1h, *K2h, *V1h, *V2h, *Kt1h, *Kt2h, *V1Tp, *V2Tp;
    __half *S16a, *S16b, *Ph, *Hh;
    float *cvec, *S1, *S2, *O1, *O2, *P, *F;
    cudaGetSymbolAddress((void**)&tex1h, g_tex1h);
    cudaGetSymbolAddress((void**)&tex2h, g_tex2h);
    cudaGetSymbolAddress((void**)&vis1h, g_vis1h);
    cudaGetSymbolAddress((void**)&vis2h, g_vis2h);
    cudaGetSymbolAddress((void**)&WqTh, g_WqTh);
    cudaGetSymbolAddress((void**)&Wkh, g_Wkh);
    cudaGetSymbolAddress((void**)&Wvh, g_Wvh);
    cudaGetSymbolAddress((void**)&Woh, g_Woh);
    cudaGetSymbolAddress((void**)&W1h, g_W1h);
    cudaGetSymbolAddress((void**)&W2h, g_W2h);
    cudaGetSymbolAddress((void**)&K1h, g_K1h);
    cudaGetSymbolAddress((void**)&K2h, g_K2h);
    cudaGetSymbolAddress((void**)&V1h, g_V1h);
    cudaGetSymbolAddress((void**)&V2h, g_V2h);
    cudaGetSymbolAddress((void**)&Kt1h, g_Kt1h);
    cudaGetSymbolAddress((void**)&Kt2h, g_Kt2h);
    cudaGetSymbolAddress((void**)&V1Tp, g_V1Tp);
    cudaGetSymbolAddress((void**)&V2Tp, g_V2Tp);
    cudaGetSymbolAddress((void**)&cvec, g_cvec);
    cudaGetSymbolAddress((void**)&S1,  g_S1);
    cudaGetSymbolAddress((void**)&S2,  g_S2);
    cudaGetSymbolAddress((void**)&S16a, g_S16a);
    cudaGetSymbolAddress((void**)&S16b, g_S16b);
    cudaGetSymbolAddress((void**)&O1,  g_O1);
    cudaGetSymbolAddress((void**)&O2,  g_O2);
    cudaGetSymbolAddress((void**)&P,   g_P);
    cudaGetSymbolAddress((void**)&Ph,  g_Ph);
    cudaGetSymbolAddress((void**)&Hh,  g_Hh);
    cudaGetSymbolAddress((void**)&F,   g_F);

    static bool attr_done = false;
    if (!attr_done) {
        cudaFuncSetAttribute(hgemm_nt,
            cudaFuncAttributeMaxDynamicSharedMemorySize, SMEM_DYN);
        attr_done = true;
    }

    const dim3 blk(256);

    // ---- one-shot conversions (Wq transposed) ----
    CvtArgs ca;
    ca.s[0] = text1; ca.d[0] = tex1h;
    ca.s[1] = text2; ca.d[1] = tex2h;
    ca.s[2] = vis1;  ca.d[2] = vis1h;
    ca.s[3] = vis2;  ca.d[3] = vis2h;
    ca.s[4] = Wq;    ca.d[4] = WqTh;
    ca.s[5] = Wk;    ca.d[5] = Wkh;
    ca.s[6] = Wv;    ca.d[6] = Wvh;
    ca.s[7] = Wo;    ca.d[7] = Woh;
    ca.s[8] = W1;    ca.d[8] = W1h;
    ca.s[9] = W2;    ca.d[9] = W2h;
    cvt_all<<<CVT_BLOCKS, blk>>>(ca);

    GemmBatch gb;
    auto E = [](const __half* A, const __half* B, const float* bias,
                const float* resid, float* oF, __half* oH, __half* oHT) {
        GemmEnt e; e.A = A; e.B = B; e.bias = bias; e.resid = resid;
        e.outF = oF; e.outH = oH; e.outHT = oHT; return e;
    };

    // ---- K/V projections (z=0..3); pad rows >= SV are zeroed ----
    gb.e[0] = E(vis1h, Wkh, bk, nullptr, nullptr, K1h, nullptr);
    gb.e[1] = E(vis1h, Wvh, bv, nullptr, nullptr, V1h, nullptr);
    gb.e[2] = E(vis2h, Wkh, bk, nullptr, nullptr, K2h, nullptr);
    gb.e[3] = E(vis2h, Wvh, bv, nullptr, nullptr, V2h, nullptr);
    hgemm_nt<<<dim3(DMODEL / BN, SVP / BM, 4), blk, SMEM_DYN>>>(
        gb, SVP, DMODEL, DMODEL, SV, 0);

    // ---- K~ = K @ Wq (via WqT), V' = V @ Wo^T (transposed out) ----
    gb.e[0] = E(K1h, WqTh, nullptr, nullptr, nullptr, Kt1h, nullptr);
    gb.e[1] = E(V1h, Woh,  nullptr, nullptr, nullptr, nullptr, V1Tp);
    gb.e[2] = E(K2h, WqTh, nullptr, nullptr, nullptr, Kt2h, nullptr);
    gb.e[3] = E(V2h, Woh,  nullptr, nullptr, nullptr, nullptr, V2Tp);
    hgemm_nt<<<dim3(DMODEL / BN, SVP / BM, 4), blk, SMEM_DYN>>>(
        gb, SVP, DMODEL, DMODEL, SVP, 0);

    // ---- cvec[k] = dot(bq, K[k]) ----
    cvec_kernel<<<dim3(SVP, 2), blk>>>(K1h, K2h, bq, cvec);

    // ---- scores: text @ K~^T (both branches) ----
    gb.e[0] = E(tex1h, Kt1h, nullptr, nullptr, S1, nullptr, nullptr);
    gb.e[1] = E(tex2h, Kt2h, nullptr, nullptr, S2, nullptr, nullptr);
    hgemm_nt<<<dim3(SVP / BN, QROWS / BM, 2), blk, SMEM_DYN>>>(
        gb, QROWS, SVP, DMODEL, QROWS, 0);

    // ---- softmax (both branches, adds cvec) ----
    softmax_kernel<<<dim3(QROWS, 2), blk>>>(S1, sc1, S16a, S2, sc2, S16b, cvec);

    // ---- O = S @ V' + bo + text (both branches) ----
    gb.e[0] = E(S16a, V1Tp, bo, text1, O1, nullptr, nullptr);
    gb.e[1] = E(S16b, V2Tp, bo, text2, O2, nullptr, nullptr);
    hgemm_nt<<<dim3(DMODEL / BN, QROWS / BM, 2), blk, SMEM_DYN>>>(
        gb, QROWS, DMODEL, SVP, QROWS, 0);

    // ---- fused LN + LN + concat-maxpool ----
    ln_pool_kernel<<<QROWS, blk>>>(O1, O2, g1, be1, P, Ph);

    // ---- FFN1 (relu) ----
    gb.e[0] = E(Ph, W1h, b1, nullptr, nullptr, Hh, nullptr);
    hgemm_nt<<<dim3(DFF / BN, QROWS / BM, 1), blk, SMEM_DYN>>>(
        gb, QROWS, DFF, DMODEL, QROWS, 1);

    // ---- FFN2 + residual ----
    gb.e[0] = E(Hh, W2h, b2, P, F, nullptr, nullptr);
    hgemm_nt<<<dim3(DMODEL / BN, QROWS / BM, 1), blk, SMEM_DYN>>>(
        gb, QROWS, DMODEL, DFF, QROWS, 0);

    // ---- final LN ----
    layernorm_kernel<<<QROWS, blk>>>(F, g2, be2, out);
}